// round 2
// baseline (speedup 1.0000x reference)
#include <cuda_runtime.h>
#include <mma.h>
using namespace nvcuda;

#define NN 50000
#define NPAD 50048    // padded rows for unguarded GEMM stores (391 * 128)
#define EE 800000
#define ETOT 850000   // EE + NN self loops
#define DIM 128       // 4 heads * 32
#define NEG 0.2f

// ---------------- scratch (device globals; no allocation allowed) ----------------
__device__ float g_xl[NPAD * DIM];    // source transform (both layers, reused)
__device__ float g_xr[NPAD * DIM];    // destination transform
__device__ float g_h1[NPAD * DIM];    // layer-1 output
__device__ float g_logits[ETOT * 4];  // CSR-ordered per-edge per-head logits (later: exp)
__device__ int   g_count[NN];
__device__ int   g_rowptr[NN + 1];
__device__ int   g_cursor[NN];
__device__ int   g_col[ETOT];         // CSR: SOURCE node id, grouped by dst
__device__ int   g_pos[ETOT];         // edge id -> CSR position

// ---------------- CSR build ----------------
__global__ void zero_counts_kernel() {
    int i = blockIdx.x * blockDim.x + threadIdx.x;
    if (i < NN) g_count[i] = 0;
}

__global__ void hist_kernel(const int* __restrict__ ei) {
    int e = blockIdx.x * blockDim.x + threadIdx.x;
    if (e >= ETOT) return;
    int dst = (e < EE) ? ei[EE + e] : (e - EE);
    atomicAdd(&g_count[dst], 1);
}

__global__ void scan_kernel() {
    const int T = 1024;
    const int CH = (NN + T - 1) / T;   // 49
    int t = threadIdx.x;
    int b = t * CH;
    int e = min(b + CH, NN);
    int s = 0;
    for (int i = b; i < e; i++) s += g_count[i];
    __shared__ int sh[T];
    sh[t] = s;
    __syncthreads();
    for (int off = 1; off < T; off <<= 1) {
        int v = (t >= off) ? sh[t - off] : 0;
        __syncthreads();
        sh[t] += v;
        __syncthreads();
    }
    int run = (t == 0) ? 0 : sh[t - 1];
    for (int i = b; i < e; i++) {
        int c = g_count[i];
        g_rowptr[i] = run;
        g_cursor[i] = run;
        run += c;
    }
    if (t == 0) g_rowptr[NN] = sh[T - 1];
}

__global__ void scatter_kernel(const int* __restrict__ ei) {
    int e = blockIdx.x * blockDim.x + threadIdx.x;
    if (e >= ETOT) return;
    int src = (e < EE) ? ei[e] : (e - EE);
    int dst = (e < EE) ? ei[EE + e] : (e - EE);
    int p = atomicAdd(&g_cursor[dst], 1);
    g_col[p] = src;
    g_pos[e] = p;
}

// ---------------- GEMM (tf32 tensor cores): C[M x 128] = A[M x 128] @ W[128 x 128] --
// 128x128 block tile, 8 warps (each 16 rows x 128 cols), K chunk 32.
// C buffers are padded to NPAD rows -> unguarded stores.
__global__ void __launch_bounds__(256) gemm_tf32_kernel(
        const float* __restrict__ A, const float* __restrict__ W,
        float* __restrict__ C, int M) {
    __shared__ float As[128][36];
    __shared__ float Bs[32][132];
    int tid = threadIdx.x;
    int warp = tid >> 5;
    int m0 = blockIdx.x * 128;

    wmma::fragment<wmma::accumulator, 16, 16, 8, float> acc[8];
    #pragma unroll
    for (int j = 0; j < 8; j++) wmma::fill_fragment(acc[j], 0.0f);

    for (int k0 = 0; k0 < 128; k0 += 32) {
        #pragma unroll
        for (int it = 0; it < 4; it++) {
            int idx = tid + it * 256;           // float4 index, 128 rows x 8 f4
            int r = idx >> 3;
            int c = (idx & 7) * 4;
            float4 v = make_float4(0.f, 0.f, 0.f, 0.f);
            int row = m0 + r;
            if (row < M) v = *(const float4*)&A[(size_t)row * 128 + k0 + c];
            *(float4*)&As[r][c] = v;
        }
        #pragma unroll
        for (int it = 0; it < 4; it++) {
            int idx = tid + it * 256;           // 32 rows x 32 f4
            int r = idx >> 5;
            int c = (idx & 31) * 4;
            *(float4*)&Bs[r][c] = *(const float4*)&W[(size_t)(k0 + r) * 128 + c];
        }
        __syncthreads();
        #pragma unroll
        for (int kk = 0; kk < 32; kk += 8) {
            wmma::fragment<wmma::matrix_a, 16, 16, 8, wmma::precision::tf32, wmma::row_major> af;
            wmma::load_matrix_sync(af, &As[warp * 16][kk], 36);
            #pragma unroll
            for (int t = 0; t < af.num_elements; t++) af.x[t] = wmma::__float_to_tf32(af.x[t]);
            #pragma unroll
            for (int j = 0; j < 8; j++) {
                wmma::fragment<wmma::matrix_b, 16, 16, 8, wmma::precision::tf32, wmma::row_major> bf;
                wmma::load_matrix_sync(bf, &Bs[kk][j * 16], 132);
                #pragma unroll
                for (int t = 0; t < bf.num_elements; t++) bf.x[t] = wmma::__float_to_tf32(bf.x[t]);
                wmma::mma_sync(acc[j], af, bf, acc[j]);
            }
        }
        __syncthreads();
    }
    #pragma unroll
    for (int j = 0; j < 8; j++)
        wmma::store_matrix_sync(&C[(size_t)(m0 + warp * 16) * 128 + j * 16],
                                acc[j], 128, wmma::mem_row_major);
}

// ---------------- Edge logits: one warp per edge, writes in CSR order ------------
__global__ void __launch_bounds__(256) logits_kernel(
        const int* __restrict__ ei, const float* __restrict__ att) {
    int gw = (blockIdx.x * blockDim.x + threadIdx.x) >> 5;
    int l = threadIdx.x & 31;
    if (gw >= ETOT) return;
    int src = (gw < EE) ? ei[gw] : gw - EE;
    int dst = (gw < EE) ? ei[EE + gw] : gw - EE;
    int p = g_pos[gw];

    float4 a = ((const float4*)att)[l];
    float4 pv = ((const float4*)g_xl)[(size_t)src * 32 + l];
    float4 qv = ((const float4*)g_xr)[(size_t)dst * 32 + l];

    float ex = pv.x + qv.x, ey = pv.y + qv.y, ez = pv.z + qv.z, ew = pv.w + qv.w;
    ex = (ex > 0.f) ? ex : NEG * ex;
    ey = (ey > 0.f) ? ey : NEG * ey;
    ez = (ez > 0.f) ? ez : NEG * ez;
    ew = (ew > 0.f) ? ew : NEG * ew;
    float s = ex * a.x + ey * a.y + ez * a.z + ew * a.w;

    s += __shfl_xor_sync(0xffffffffu, s, 1, 8);
    s += __shfl_xor_sync(0xffffffffu, s, 2, 8);
    s += __shfl_xor_sync(0xffffffffu, s, 4, 8);
    if ((l & 7) == 0) g_logits[(size_t)p * 4 + (l >> 3)] = s;
}

// ---------------- Softmax + aggregate: one warp per destination node -------------
// mode 0: g_h1 = relu(agg + b)              (concat over heads, 128-wide)
// mode 1: outp = relu(mean_h(agg) + b)      (32-wide)
__global__ void __launch_bounds__(256) agg_kernel(
        const float* __restrict__ bias, float* __restrict__ outp, int mode) {
    int d = (blockIdx.x * blockDim.x + threadIdx.x) >> 5;
    int l = threadIdx.x & 31;
    if (d >= NN) return;
    int s0 = g_rowptr[d], s1 = g_rowptr[d + 1];

    // pass 1: per-head max (sequential, coalesced)
    float4 mx = make_float4(-1e30f, -1e30f, -1e30f, -1e30f);
    for (int i = s0 + l; i < s1; i += 32) {
        float4 lg = ((const float4*)g_logits)[i];
        mx.x = fmaxf(mx.x, lg.x); mx.y = fmaxf(mx.y, lg.y);
        mx.z = fmaxf(mx.z, lg.z); mx.w = fmaxf(mx.w, lg.w);
    }
    #pragma unroll
    for (int off = 16; off; off >>= 1) {
        mx.x = fmaxf(mx.x, __shfl_xor_sync(0xffffffffu, mx.x, off));
        mx.y = fmaxf(mx.y, __shfl_xor_sync(0xffffffffu, mx.y, off));
        mx.z = fmaxf(mx.z, __shfl_xor_sync(0xffffffffu, mx.z, off));
        mx.w = fmaxf(mx.w, __shfl_xor_sync(0xffffffffu, mx.w, off));
    }

    // pass 2: exp + per-head sum; store exp back (sequential)
    float4 se = make_float4(0.f, 0.f, 0.f, 0.f);
    for (int i = s0 + l; i < s1; i += 32) {
        float4 lg = ((const float4*)g_logits)[i];
        float4 aa;
        aa.x = __expf(lg.x - mx.x); aa.y = __expf(lg.y - mx.y);
        aa.z = __expf(lg.z - mx.z); aa.w = __expf(lg.w - mx.w);
        ((float4*)g_logits)[i] = aa;
        se.x += aa.x; se.y += aa.y; se.z += aa.z; se.w += aa.w;
    }
    #pragma unroll
    for (int off = 16; off; off >>= 1) {
        se.x += __shfl_xor_sync(0xffffffffu, se.x, off);
        se.y += __shfl_xor_sync(0xffffffffu, se.y, off);
        se.z += __shfl_xor_sync(0xffffffffu, se.z, off);
        se.w += __shfl_xor_sync(0xffffffffu, se.w, off);
    }
    __syncwarp();

    int head = l >> 3;
    float dn = (head == 0) ? se.x : (head == 1) ? se.y : (head == 2) ? se.z : se.w;
    float invdn = 1.0f / dn;

    // pass 3: weighted aggregation, 4x unrolled for gather MLP
    float4 acc = make_float4(0.f, 0.f, 0.f, 0.f);
    int i = s0;
    for (; i + 4 <= s1; i += 4) {
        int sA = g_col[i + 0], sB = g_col[i + 1], sC = g_col[i + 2], sD = g_col[i + 3];
        float wA = g_logits[(size_t)(i + 0) * 4 + head] * invdn;
        float wB = g_logits[(size_t)(i + 1) * 4 + head] * invdn;
        float wC = g_logits[(size_t)(i + 2) * 4 + head] * invdn;
        float wD = g_logits[(size_t)(i + 3) * 4 + head] * invdn;
        float4 vA = ((const float4*)g_xl)[(size_t)sA * 32 + l];
        float4 vB = ((const float4*)g_xl)[(size_t)sB * 32 + l];
        float4 vC = ((const float4*)g_xl)[(size_t)sC * 32 + l];
        float4 vD = ((const float4*)g_xl)[(size_t)sD * 32 + l];
        acc.x += vA.x * wA + vB.x * wB + vC.x * wC + vD.x * wD;
        acc.y += vA.y * wA + vB.y * wB + vC.y * wC + vD.y * wD;
        acc.z += vA.z * wA + vB.z * wB + vC.z * wC + vD.z * wD;
        acc.w += vA.w * wA + vB.w * wB + vC.w * wC + vD.w * wD;
    }
    for (; i < s1; i++) {
        int sA = g_col[i];
        float w = g_logits[(size_t)i * 4 + head] * invdn;
        float4 v = ((const float4*)g_xl)[(size_t)sA * 32 + l];
        acc.x += v.x * w; acc.y += v.y * w; acc.z += v.z * w; acc.w += v.w * w;
    }

    if (mode == 0) {
        float4 b = ((const float4*)bias)[l];
        float4 o;
        o.x = fmaxf(acc.x + b.x, 0.f);
        o.y = fmaxf(acc.y + b.y, 0.f);
        o.z = fmaxf(acc.z + b.z, 0.f);
        o.w = fmaxf(acc.w + b.w, 0.f);
        ((float4*)g_h1)[(size_t)d * 32 + l] = o;
    } else {
        acc.x += __shfl_xor_sync(0xffffffffu, acc.x, 8);
        acc.y += __shfl_xor_sync(0xffffffffu, acc.y, 8);
        acc.z += __shfl_xor_sync(0xffffffffu, acc.z, 8);
        acc.w += __shfl_xor_sync(0xffffffffu, acc.w, 8);
        acc.x += __shfl_xor_sync(0xffffffffu, acc.x, 16);
        acc.y += __shfl_xor_sync(0xffffffffu, acc.y, 16);
        acc.z += __shfl_xor_sync(0xffffffffu, acc.z, 16);
        acc.w += __shfl_xor_sync(0xffffffffu, acc.w, 16);
        if (l < 8) {
            float4 b = ((const float4*)bias)[l];
            float4 o;
            o.x = fmaxf(acc.x * 0.25f + b.x, 0.f);
            o.y = fmaxf(acc.y * 0.25f + b.y, 0.f);
            o.z = fmaxf(acc.z * 0.25f + b.z, 0.f);
            o.w = fmaxf(acc.w * 0.25f + b.w, 0.f);
            ((float4*)outp)[(size_t)d * 8 + l] = o;
        }
    }
}

// ---------------- launch ----------------
extern "C" void kernel_launch(void* const* d_in, const int* in_sizes, int n_in,
                              void* d_out, int out_size) {
    const float* x    = (const float*)d_in[0];
    const int*   ei   = (const int*)d_in[1];
    const float* Wl1  = (const float*)d_in[2];
    const float* Wr1  = (const float*)d_in[3];
    const float* att1 = (const float*)d_in[4];
    const float* b1   = (const float*)d_in[5];
    const float* Wl2  = (const float*)d_in[6];
    const float* Wr2  = (const float*)d_in[7];
    const float* att2 = (const float*)d_in[8];
    const float* b2   = (const float*)d_in[9];
    float* out = (float*)d_out;

    float* d_xl; cudaGetSymbolAddress((void**)&d_xl, g_xl);
    float* d_xr; cudaGetSymbolAddress((void**)&d_xr, g_xr);
    float* d_h1; cudaGetSymbolAddress((void**)&d_h1, g_h1);

    // CSR by destination (same for both layers)
    zero_counts_kernel<<<(NN + 255) / 256, 256>>>();
    hist_kernel<<<(ETOT + 255) / 256, 256>>>(ei);
    scan_kernel<<<1, 1024>>>();
    scatter_kernel<<<(ETOT + 255) / 256, 256>>>(ei);

    int gemm_blocks = (NN + 127) / 128;   // 391
    int logit_blocks = (int)(((long long)ETOT * 32 + 255) / 256);
    int agg_blocks = (NN * 32 + 255) / 256;

    // ---- layer 1 ----
    gemm_tf32_kernel<<<gemm_blocks, 256>>>(x, Wl1, d_xl, NN);
    gemm_tf32_kernel<<<gemm_blocks, 256>>>(x, Wr1, d_xr, NN);
    logits_kernel<<<logit_blocks, 256>>>(ei, att1);
    agg_kernel<<<agg_blocks, 256>>>(b1, nullptr, 0);   // -> g_h1 (relu)

    // ---- layer 2 ----
    gemm_tf32_kernel<<<gemm_blocks, 256>>>(d_h1, Wl2, d_xl, NN);
    gemm_tf32_kernel<<<gemm_blocks, 256>>>(d_h1, Wr2, d_xr, NN);
    logits_kernel<<<logit_blocks, 256>>>(ei, att2);
    agg_kernel<<<agg_blocks, 256>>>(b2, out, 1);       // -> d_out (relu of head-mean)
}

// round 6
// speedup vs baseline: 1.5670x; 1.5670x over previous
#include <cuda_runtime.h>
#include <cuda_fp16.h>

#define NN 50000
#define NPAD 50048    // 782 * 64, padded rows for unguarded stores
#define EE 800000
#define ETOT 850000   // EE + NN self loops
#define DIM 128       // 4 heads * 32
#define NEG 0.2f

// ---------------- scratch (device globals; no allocation allowed) ----------------
// fp16 edge tables stored as uint2 (4 halves per element) -> guaranteed 8B alignment.
// Row = 32 uint2 = 128 halves.
__device__ uint2 g_xlh[NPAD * 32];   // source transform, fp16
__device__ uint2 g_xrh[NPAD * 32];   // destination transform, fp16
__device__ float g_h1[NPAD * DIM];   // layer-1 output, fp32 (GEMM input)
__device__ int   g_count[NN];
__device__ int   g_rowptr[NN + 1];
__device__ int   g_cursor[NN];
__device__ int   g_col[ETOT];        // CSR: SOURCE node id, grouped by dst

// ---------------- CSR build ----------------
__global__ void zero_counts_kernel() {
    int i = blockIdx.x * blockDim.x + threadIdx.x;
    if (i < NN) g_count[i] = 0;
}

__global__ void hist_kernel(const int* __restrict__ ei) {
    int e = blockIdx.x * blockDim.x + threadIdx.x;
    if (e >= ETOT) return;
    int dst = (e < EE) ? ei[EE + e] : (e - EE);
    atomicAdd(&g_count[dst], 1);
}

__global__ void scan_kernel() {
    const int T = 1024;
    const int CH = (NN + T - 1) / T;   // 49
    int t = threadIdx.x;
    int b = t * CH;
    int e = min(b + CH, NN);
    int s = 0;
    for (int i = b; i < e; i++) s += g_count[i];
    __shared__ int sh[T];
    sh[t] = s;
    __syncthreads();
    for (int off = 1; off < T; off <<= 1) {
        int v = (t >= off) ? sh[t - off] : 0;
        __syncthreads();
        sh[t] += v;
        __syncthreads();
    }
    int run = (t == 0) ? 0 : sh[t - 1];
    for (int i = b; i < e; i++) {
        int c = g_count[i];
        g_rowptr[i] = run;
        g_cursor[i] = run;
        run += c;
    }
    if (t == 0) g_rowptr[NN] = sh[T - 1];
}

__global__ void scatter_kernel(const int* __restrict__ ei) {
    int e = blockIdx.x * blockDim.x + threadIdx.x;
    if (e >= ETOT) return;
    int src = (e < EE) ? ei[e] : (e - EE);
    int dst = (e < EE) ? ei[EE + e] : (e - EE);
    int p = atomicAdd(&g_cursor[dst], 1);
    g_col[p] = src;
}

// ---------------- Fused dual GEMM (fp32 SIMT): Cl = A@Wl, Cr = A@Wr --------------
// 64x64 tile per output, 256 threads, 4x4 micro-tile per output, BK=32.
// A tile loaded once, used for both weight matrices. Outputs stored as fp16 (uint2).
// Shared rows padded to 16-byte multiples (36 / 68 floats) for float4 access.
__global__ void __launch_bounds__(256) gemm_dual_kernel(
        const float* __restrict__ A, const float* __restrict__ Wl,
        const float* __restrict__ Wr, int M) {
    __shared__ float As[64][36];   // 144 B row stride (16-mult)
    __shared__ float Bl[32][68];   // 272 B row stride (16-mult)
    __shared__ float Br[32][68];

    int tid = threadIdx.x;
    int tx = tid & 15;
    int ty = tid >> 4;
    int m0 = blockIdx.x * 64;
    int n0 = blockIdx.y * 64;

    float accl[4][4] = {};
    float accr[4][4] = {};

    for (int k0 = 0; k0 < 128; k0 += 32) {
        {
            int r = tid >> 3, kq = (tid & 7) * 4;
            float4 v = make_float4(0.f, 0.f, 0.f, 0.f);
            if (m0 + r < M) v = *(const float4*)&A[(size_t)(m0 + r) * 128 + k0 + kq];
            *(float4*)&As[r][kq] = v;
            float4 v2 = make_float4(0.f, 0.f, 0.f, 0.f);
            if (m0 + r + 32 < M) v2 = *(const float4*)&A[(size_t)(m0 + r + 32) * 128 + k0 + kq];
            *(float4*)&As[r + 32][kq] = v2;
        }
        {
            int kk = tid >> 4, c4 = (tid & 15) * 4;
            *(float4*)&Bl[kk][c4]      = *(const float4*)&Wl[(size_t)(k0 + kk) * 128 + n0 + c4];
            *(float4*)&Bl[kk + 16][c4] = *(const float4*)&Wl[(size_t)(k0 + kk + 16) * 128 + n0 + c4];
            *(float4*)&Br[kk][c4]      = *(const float4*)&Wr[(size_t)(k0 + kk) * 128 + n0 + c4];
            *(float4*)&Br[kk + 16][c4] = *(const float4*)&Wr[(size_t)(k0 + kk + 16) * 128 + n0 + c4];
        }
        __syncthreads();
        #pragma unroll
        for (int k = 0; k < 32; k++) {
            float4 bl = *(const float4*)&Bl[k][tx * 4];
            float4 br = *(const float4*)&Br[k][tx * 4];
            float a0 = As[ty * 4 + 0][k];
            float a1 = As[ty * 4 + 1][k];
            float a2 = As[ty * 4 + 2][k];
            float a3 = As[ty * 4 + 3][k];
            accl[0][0] += a0 * bl.x; accl[0][1] += a0 * bl.y; accl[0][2] += a0 * bl.z; accl[0][3] += a0 * bl.w;
            accl[1][0] += a1 * bl.x; accl[1][1] += a1 * bl.y; accl[1][2] += a1 * bl.z; accl[1][3] += a1 * bl.w;
            accl[2][0] += a2 * bl.x; accl[2][1] += a2 * bl.y; accl[2][2] += a2 * bl.z; accl[2][3] += a2 * bl.w;
            accl[3][0] += a3 * bl.x; accl[3][1] += a3 * bl.y; accl[3][2] += a3 * bl.z; accl[3][3] += a3 * bl.w;
            accr[0][0] += a0 * br.x; accr[0][1] += a0 * br.y; accr[0][2] += a0 * br.z; accr[0][3] += a0 * br.w;
            accr[1][0] += a1 * br.x; accr[1][1] += a1 * br.y; accr[1][2] += a1 * br.z; accr[1][3] += a1 * br.w;
            accr[2][0] += a2 * br.x; accr[2][1] += a2 * br.y; accr[2][2] += a2 * br.z; accr[2][3] += a2 * br.w;
            accr[3][0] += a3 * br.x; accr[3][1] += a3 * br.y; accr[3][2] += a3 * br.z; accr[3][3] += a3 * br.w;
        }
        __syncthreads();
    }
    #pragma unroll
    for (int i = 0; i < 4; i++) {
        int m = m0 + ty * 4 + i;   // always < NPAD (grid covers exactly NPAD rows)
        size_t off = (size_t)m * 32 + (n0 >> 2) + tx;   // uint2 index (4 halves each)
        __half2 l0 = __floats2half2_rn(accl[i][0], accl[i][1]);
        __half2 l1 = __floats2half2_rn(accl[i][2], accl[i][3]);
        __half2 r0 = __floats2half2_rn(accr[i][0], accr[i][1]);
        __half2 r1 = __floats2half2_rn(accr[i][2], accr[i][3]);
        uint2 ul, ur;
        ul.x = *(unsigned*)&l0; ul.y = *(unsigned*)&l1;
        ur.x = *(unsigned*)&r0; ur.y = *(unsigned*)&r1;
        g_xlh[off] = ul;
        g_xrh[off] = ur;
    }
}

// ---------------- Fused online-softmax GAT aggregation ----------------
// One warp per destination node. Single pass over edges:
// gather xl[src] (fp16) once per edge, compute logit, online softmax accumulate.
// mode 0: g_h1 = relu(agg + b)          (concat heads, 128-wide fp32)
// mode 1: outp = relu(mean_h(agg) + b)  (32-wide fp32)
__global__ void __launch_bounds__(256) agg_fused_kernel(
        const float* __restrict__ att, const float* __restrict__ bias,
        float* __restrict__ outp, int mode) {
    int d = (blockIdx.x * blockDim.x + threadIdx.x) >> 5;
    int l = threadIdx.x & 31;
    if (d >= NN) return;
    int s0 = g_rowptr[d], s1 = g_rowptr[d + 1];

    // att + xr[dst], lane l owns feature dims [4l, 4l+4) (head = l>>3)
    float4 a4 = ((const float4*)att)[l];
    uint2 qraw = g_xrh[(size_t)d * 32 + l];
    float2 q01 = __half22float2(*(__half2*)&qraw.x);
    float2 q23 = __half22float2(*(__half2*)&qraw.y);

    float m = -1e30f, den = 0.f;
    float4 acc = make_float4(0.f, 0.f, 0.f, 0.f);

    // software-pipelined edge loop: prefetch next src row while computing current
    int src_n = (s0 < s1) ? g_col[s0] : 0;
    uint2 raw_n = make_uint2(0u, 0u);
    if (s0 < s1) raw_n = g_xlh[(size_t)src_n * 32 + l];

    for (int i = s0; i < s1; i++) {
        uint2 raw = raw_n;
        if (i + 1 < s1) {
            int sn = g_col[i + 1];
            raw_n = g_xlh[(size_t)sn * 32 + l];
        }
        float2 v01 = __half22float2(*(__half2*)&raw.x);
        float2 v23 = __half22float2(*(__half2*)&raw.y);

        float ex = v01.x + q01.x, ey = v01.y + q01.y;
        float ez = v23.x + q23.x, ew = v23.y + q23.y;
        float lx = (ex > 0.f) ? ex : NEG * ex;
        float ly = (ey > 0.f) ? ey : NEG * ey;
        float lz = (ez > 0.f) ? ez : NEG * ez;
        float lw = (ew > 0.f) ? ew : NEG * ew;
        float t = lx * a4.x + ly * a4.y + lz * a4.z + lw * a4.w;
        // reduce within each 8-lane head group
        t += __shfl_xor_sync(0xffffffffu, t, 1, 8);
        t += __shfl_xor_sync(0xffffffffu, t, 2, 8);
        t += __shfl_xor_sync(0xffffffffu, t, 4, 8);

        // online softmax update (per head; every lane in the group has the same t)
        float mnew = fmaxf(m, t);
        float corr = __expf(m - mnew);
        float w = __expf(t - mnew);
        den = den * corr + w;
        acc.x = acc.x * corr + w * v01.x;
        acc.y = acc.y * corr + w * v01.y;
        acc.z = acc.z * corr + w * v23.x;
        acc.w = acc.w * corr + w * v23.y;
        m = mnew;
    }

    float invdn = 1.0f / den;
    acc.x *= invdn; acc.y *= invdn; acc.z *= invdn; acc.w *= invdn;

    if (mode == 0) {
        float4 b = ((const float4*)bias)[l];
        float4 o;
        o.x = fmaxf(acc.x + b.x, 0.f);
        o.y = fmaxf(acc.y + b.y, 0.f);
        o.z = fmaxf(acc.z + b.z, 0.f);
        o.w = fmaxf(acc.w + b.w, 0.f);
        ((float4*)g_h1)[(size_t)d * 32 + l] = o;
    } else {
        // mean over heads: sum lanes {l, l+8, l+16, l+24} (after the divide)
        acc.x += __shfl_xor_sync(0xffffffffu, acc.x, 8);
        acc.y += __shfl_xor_sync(0xffffffffu, acc.y, 8);
        acc.z += __shfl_xor_sync(0xffffffffu, acc.z, 8);
        acc.w += __shfl_xor_sync(0xffffffffu, acc.w, 8);
        acc.x += __shfl_xor_sync(0xffffffffu, acc.x, 16);
        acc.y += __shfl_xor_sync(0xffffffffu, acc.y, 16);
        acc.z += __shfl_xor_sync(0xffffffffu, acc.z, 16);
        acc.w += __shfl_xor_sync(0xffffffffu, acc.w, 16);
        if (l < 8) {
            float4 b = ((const float4*)bias)[l];
            float4 o;
            o.x = fmaxf(acc.x * 0.25f + b.x, 0.f);
            o.y = fmaxf(acc.y * 0.25f + b.y, 0.f);
            o.z = fmaxf(acc.z * 0.25f + b.z, 0.f);
            o.w = fmaxf(acc.w * 0.25f + b.w, 0.f);
            ((float4*)outp)[(size_t)d * 8 + l] = o;
        }
    }
}

// ---------------- launch ----------------
extern "C" void kernel_launch(void* const* d_in, const int* in_sizes, int n_in,
                              void* d_out, int out_size) {
    const float* x    = (const float*)d_in[0];
    const int*   ei   = (const int*)d_in[1];
    const float* Wl1  = (const float*)d_in[2];
    const float* Wr1  = (const float*)d_in[3];
    const float* att1 = (const float*)d_in[4];
    const float* b1   = (const float*)d_in[5];
    const float* Wl2  = (const float*)d_in[6];
    const float* Wr2  = (const float*)d_in[7];
    const float* att2 = (const float*)d_in[8];
    const float* b2   = (const float*)d_in[9];
    float* out = (float*)d_out;

    float* d_h1; cudaGetSymbolAddress((void**)&d_h1, g_h1);

    // CSR by destination (same for both layers)
    zero_counts_kernel<<<(NN + 255) / 256, 256>>>();
    hist_kernel<<<(ETOT + 255) / 256, 256>>>(ei);
    scan_kernel<<<1, 1024>>>();
    scatter_kernel<<<(ETOT + 255) / 256, 256>>>(ei);

    dim3 gg(NPAD / 64, 2);                         // 782 x 2
    int agg_blocks = (NN * 32 + 255) / 256;        // one warp per dst

    // ---- layer 1 ----
    gemm_dual_kernel<<<gg, 256>>>(x, Wl1, Wr1, NN);       // -> g_xlh, g_xrh (fp16)
    agg_fused_kernel<<<agg_blocks, 256>>>(att1, b1, nullptr, 0);   // -> g_h1 (fp32, relu)

    // ---- layer 2 ----
    gemm_dual_kernel<<<gg, 256>>>(d_h1, Wl2, Wr2, NN);    // -> g_xlh, g_xrh (fp16)
    agg_fused_kernel<<<agg_blocks, 256>>>(att2, b2, out, 1);       // -> d_out
}

// round 7
// speedup vs baseline: 1.6530x; 1.0549x over previous
#include <cuda_runtime.h>
#include <cuda_fp16.h>
#include <mma.h>
using namespace nvcuda;

#define NN 50000
#define NPAD 50048    // 782 * 64, padded rows for unguarded stores
#define EE 800000
#define ETOT 850000   // EE + NN self loops
#define DIM 128       // 4 heads * 32
#define NEG 0.2f

// ---------------- scratch (device globals; no allocation allowed) ----------------
__device__ uint2 g_xlh[NPAD * 32];   // source transform, fp16 (4 halves per uint2)
__device__ uint2 g_xrh[NPAD * 32];   // destination transform, fp16
__device__ float g_h1[NPAD * DIM];   // layer-1 output, fp32 (GEMM input)
__device__ int   g_count[NN];
__device__ int   g_rowptr[NN + 1];
__device__ int   g_cursor[NN];
__device__ int   g_col[ETOT];        // CSR: SOURCE node id, grouped by dst

// ---------------- CSR build ----------------
__global__ void zero_counts_kernel() {
    int i = blockIdx.x * blockDim.x + threadIdx.x;
    if (i < NN) g_count[i] = 0;
}

__global__ void hist_kernel(const int* __restrict__ ei) {
    int e = blockIdx.x * blockDim.x + threadIdx.x;
    if (e >= ETOT) return;
    int dst = (e < EE) ? ei[EE + e] : (e - EE);
    atomicAdd(&g_count[dst], 1);
}

__global__ void scan_kernel() {
    const int T = 1024;
    const int CH = (NN + T - 1) / T;   // 49
    int t = threadIdx.x;
    int b = t * CH;
    int e = min(b + CH, NN);
    int s = 0;
    for (int i = b; i < e; i++) s += g_count[i];
    __shared__ int sh[T];
    sh[t] = s;
    __syncthreads();
    for (int off = 1; off < T; off <<= 1) {
        int v = (t >= off) ? sh[t - off] : 0;
        __syncthreads();
        sh[t] += v;
        __syncthreads();
    }
    int run = (t == 0) ? 0 : sh[t - 1];
    for (int i = b; i < e; i++) {
        int c = g_count[i];
        g_rowptr[i] = run;
        g_cursor[i] = run;
        run += c;
    }
    if (t == 0) g_rowptr[NN] = sh[T - 1];
}

__global__ void scatter_kernel(const int* __restrict__ ei) {
    int e = blockIdx.x * blockDim.x + threadIdx.x;
    if (e >= ETOT) return;
    int src = (e < EE) ? ei[e] : (e - EE);
    int dst = (e < EE) ? ei[EE + e] : (e - EE);
    int p = atomicAdd(&g_cursor[dst], 1);
    g_col[p] = src;
}

// ---------------- Dual GEMM via fp16 tensor cores (HMMA m16n16k16) --------------
// Per block: 64 rows x 256 cols (Wl's 128 ++ Wr's 128), K=128 in 32-chunks.
// 8 warps: warp w -> row group (w&3)*16, half (w>>2) selects Wl/Wr; 8 acc frags.
// A and W converted fp32->fp16 on smem load. Epilogue: 2 waves through fp32 smem,
// converted to fp16 and stored to g_xlh / g_xrh.
__global__ void __launch_bounds__(256) gemm_half_kernel(
        const float* __restrict__ A, const float* __restrict__ Wl,
        const float* __restrict__ Wr, int M) {
    __shared__ __align__(16) float Cs[64][132];               // 33792 B
    __half* As = (__half*)&Cs[0][0];                          // 64 x 48 halves (6144 B)
    __half* Ws = (__half*)((char*)&Cs[0][0] + 8192);          // 32 x 264 halves (16896 B)

    int tid = threadIdx.x;
    int w = tid >> 5;
    int rg = w & 3;      // row group (16 rows)
    int hf = w >> 2;     // 0 = Wl half, 1 = Wr half

    int m0 = blockIdx.x * 64;

    wmma::fragment<wmma::accumulator, 16, 16, 16, float> acc[8];
    #pragma unroll
    for (int j = 0; j < 8; j++) wmma::fill_fragment(acc[j], 0.0f);

    for (int k0 = 0; k0 < 128; k0 += 32) {
        // A chunk 64x32 -> fp16 smem
        {
            int r = tid >> 2, c = (tid & 3) * 8;
            float4 f0 = make_float4(0.f, 0.f, 0.f, 0.f), f1 = f0;
            if (m0 + r < M) {
                const float* p = &A[(size_t)(m0 + r) * 128 + k0 + c];
                f0 = *(const float4*)p;
                f1 = *(const float4*)(p + 4);
            }
            __half2 h0 = __floats2half2_rn(f0.x, f0.y);
            __half2 h1 = __floats2half2_rn(f0.z, f0.w);
            __half2 h2 = __floats2half2_rn(f1.x, f1.y);
            __half2 h3 = __floats2half2_rn(f1.z, f1.w);
            uint4 u;
            u.x = *(unsigned*)&h0; u.y = *(unsigned*)&h1;
            u.z = *(unsigned*)&h2; u.w = *(unsigned*)&h3;
            *(uint4*)&As[r * 48 + c] = u;
        }
        // W chunk 32 x 256 (Wl cols 0-127, Wr cols 128-255) -> fp16 smem
        {
            int kk = tid >> 3, c = (tid & 7) * 32;
            const float* src = (c < 128) ? Wl : Wr;
            int scol = c & 127;
            const float* p = &src[(size_t)(k0 + kk) * 128 + scol];
            #pragma unroll
            for (int q = 0; q < 4; q++) {
                float4 f0 = *(const float4*)(p + q * 8);
                float4 f1 = *(const float4*)(p + q * 8 + 4);
                __half2 h0 = __floats2half2_rn(f0.x, f0.y);
                __half2 h1 = __floats2half2_rn(f0.z, f0.w);
                __half2 h2 = __floats2half2_rn(f1.x, f1.y);
                __half2 h3 = __floats2half2_rn(f1.z, f1.w);
                uint4 u;
                u.x = *(unsigned*)&h0; u.y = *(unsigned*)&h1;
                u.z = *(unsigned*)&h2; u.w = *(unsigned*)&h3;
                *(uint4*)&Ws[kk * 264 + c + q * 8] = u;
            }
        }
        __syncthreads();
        #pragma unroll
        for (int ks = 0; ks < 32; ks += 16) {
            wmma::fragment<wmma::matrix_a, 16, 16, 16, __half, wmma::row_major> af;
            wmma::load_matrix_sync(af, &As[(rg * 16) * 48 + ks], 48);
            #pragma unroll
            for (int j = 0; j < 8; j++) {
                wmma::fragment<wmma::matrix_b, 16, 16, 16, __half, wmma::row_major> bf;
                wmma::load_matrix_sync(bf, &Ws[ks * 264 + hf * 128 + j * 16], 264);
                wmma::mma_sync(acc[j], af, bf, acc[j]);
            }
        }
        __syncthreads();
    }

    // Epilogue: two waves (Wl then Wr) through fp32 smem, convert to fp16, store.
    #pragma unroll
    for (int wave = 0; wave < 2; wave++) {
        if (hf == wave) {
            #pragma unroll
            for (int j = 0; j < 8; j++)
                wmma::store_matrix_sync(&Cs[rg * 16][j * 16], acc[j], 132, wmma::mem_row_major);
        }
        __syncthreads();
        {
            int r = tid >> 2, cb = (tid & 3) * 8;   // uint2 index within row (32/row)
            uint2* dst = wave ? g_xrh : g_xlh;
            size_t base = (size_t)(m0 + r) * 32 + cb;
            #pragma unroll
            for (int j = 0; j < 8; j++) {
                float4 f = *(const float4*)&Cs[r][(cb + j) * 4];
                __half2 h0 = __floats2half2_rn(f.x, f.y);
                __half2 h1 = __floats2half2_rn(f.z, f.w);
                uint2 u;
                u.x = *(unsigned*)&h0; u.y = *(unsigned*)&h1;
                dst[base + j] = u;
            }
        }
        __syncthreads();
    }
}

// ---------------- Fused online-softmax GAT aggregation ----------------
// One warp per destination node; depth-2 prefetch of gathered fp16 rows.
// mode 0: g_h1 = relu(agg + b)          (concat heads, 128-wide fp32)
// mode 1: outp = relu(mean_h(agg) + b)  (32-wide fp32)
__global__ void __launch_bounds__(256) agg_fused_kernel(
        const float* __restrict__ att, const float* __restrict__ bias,
        float* __restrict__ outp, int mode) {
    int d = (blockIdx.x * blockDim.x + threadIdx.x) >> 5;
    int l = threadIdx.x & 31;
    if (d >= NN) return;
    int s0 = g_rowptr[d], s1 = g_rowptr[d + 1];

    float4 a4 = ((const float4*)att)[l];
    uint2 qraw = g_xrh[(size_t)d * 32 + l];
    float2 q01 = __half22float2(*(__half2*)&qraw.x);
    float2 q23 = __half22float2(*(__half2*)&qraw.y);

    float m = -1e30f, den = 0.f;
    float4 acc = make_float4(0.f, 0.f, 0.f, 0.f);

    uint2 p0 = make_uint2(0u, 0u), p1 = make_uint2(0u, 0u);
    if (s0 < s1)     p0 = g_xlh[(size_t)g_col[s0] * 32 + l];
    if (s0 + 1 < s1) p1 = g_xlh[(size_t)g_col[s0 + 1] * 32 + l];

    for (int i = s0; i < s1; i++) {
        uint2 raw = p0;
        p0 = p1;
        if (i + 2 < s1) p1 = g_xlh[(size_t)g_col[i + 2] * 32 + l];

        float2 v01 = __half22float2(*(__half2*)&raw.x);
        float2 v23 = __half22float2(*(__half2*)&raw.y);

        float ex = v01.x + q01.x, ey = v01.y + q01.y;
        float ez = v23.x + q23.x, ew = v23.y + q23.y;
        float lx = (ex > 0.f) ? ex : NEG * ex;
        float ly = (ey > 0.f) ? ey : NEG * ey;
        float lz = (ez > 0.f) ? ez : NEG * ez;
        float lw = (ew > 0.f) ? ew : NEG * ew;
        float t = lx * a4.x + ly * a4.y + lz * a4.z + lw * a4.w;
        t += __shfl_xor_sync(0xffffffffu, t, 1, 8);
        t += __shfl_xor_sync(0xffffffffu, t, 2, 8);
        t += __shfl_xor_sync(0xffffffffu, t, 4, 8);

        float mnew = fmaxf(m, t);
        float corr = __expf(m - mnew);
        float w = __expf(t - mnew);
        den = den * corr + w;
        acc.x = acc.x * corr + w * v01.x;
        acc.y = acc.y * corr + w * v01.y;
        acc.z = acc.z * corr + w * v23.x;
        acc.w = acc.w * corr + w * v23.y;
        m = mnew;
    }

    float invdn = 1.0f / den;
    acc.x *= invdn; acc.y *= invdn; acc.z *= invdn; acc.w *= invdn;

    if (mode == 0) {
        float4 b = ((const float4*)bias)[l];
        float4 o;
        o.x = fmaxf(acc.x + b.x, 0.f);
        o.y = fmaxf(acc.y + b.y, 0.f);
        o.z = fmaxf(acc.z + b.z, 0.f);
        o.w = fmaxf(acc.w + b.w, 0.f);
        ((float4*)g_h1)[(size_t)d * 32 + l] = o;
    } else {
        acc.x += __shfl_xor_sync(0xffffffffu, acc.x, 8);
        acc.y += __shfl_xor_sync(0xffffffffu, acc.y, 8);
        acc.z += __shfl_xor_sync(0xffffffffu, acc.z, 8);
        acc.w += __shfl_xor_sync(0xffffffffu, acc.w, 8);
        acc.x += __shfl_xor_sync(0xffffffffu, acc.x, 16);
        acc.y += __shfl_xor_sync(0xffffffffu, acc.y, 16);
        acc.z += __shfl_xor_sync(0xffffffffu, acc.z, 16);
        acc.w += __shfl_xor_sync(0xffffffffu, acc.w, 16);
        if (l < 8) {
            float4 b = ((const float4*)bias)[l];
            float4 o;
            o.x = fmaxf(acc.x * 0.25f + b.x, 0.f);
            o.y = fmaxf(acc.y * 0.25f + b.y, 0.f);
            o.z = fmaxf(acc.z * 0.25f + b.z, 0.f);
            o.w = fmaxf(acc.w * 0.25f + b.w, 0.f);
            ((float4*)outp)[(size_t)d * 8 + l] = o;
        }
    }
}

// ---------------- launch ----------------
extern "C" void kernel_launch(void* const* d_in, const int* in_sizes, int n_in,
                              void* d_out, int out_size) {
    const float* x    = (const float*)d_in[0];
    const int*   ei   = (const int*)d_in[1];
    const float* Wl1  = (const float*)d_in[2];
    const float* Wr1  = (const float*)d_in[3];
    const float* att1 = (const float*)d_in[4];
    const float* b1   = (const float*)d_in[5];
    const float* Wl2  = (const float*)d_in[6];
    const float* Wr2  = (const float*)d_in[7];
    const float* att2 = (const float*)d_in[8];
    const float* b2   = (const float*)d_in[9];
    float* out = (float*)d_out;

    float* d_h1; cudaGetSymbolAddress((void**)&d_h1, g_h1);

    // CSR by destination (same for both layers)
    zero_counts_kernel<<<(NN + 255) / 256, 256>>>();
    hist_kernel<<<(ETOT + 255) / 256, 256>>>(ei);
    scan_kernel<<<1, 1024>>>();
    scatter_kernel<<<(ETOT + 255) / 256, 256>>>(ei);

    int gemm_blocks = NPAD / 64;                   // 782
    int agg_blocks = (NN * 32 + 255) / 256;        // one warp per dst

    // ---- layer 1 ----
    gemm_half_kernel<<<gemm_blocks, 256>>>(x, Wl1, Wr1, NN);       // -> g_xlh, g_xrh
    agg_fused_kernel<<<agg_blocks, 256>>>(att1, b1, nullptr, 0);   // -> g_h1 (relu)

    // ---- layer 2 ----
    gemm_half_kernel<<<gemm_blocks, 256>>>(d_h1, Wl2, Wr2, NN);    // -> g_xlh, g_xrh
    agg_fused_kernel<<<agg_blocks, 256>>>(att2, b2, out, 1);       // -> d_out
}

// round 8
// speedup vs baseline: 1.7422x; 1.0540x over previous
#include <cuda_runtime.h>
#include <cuda_fp16.h>
#include <mma.h>
using namespace nvcuda;

#define NN 50000
#define NPAD 50048    // 391 * 128, padded rows for unguarded stores
#define EE 800000
#define ETOT 850000   // EE + NN self loops
#define DIM 128       // 4 heads * 32
#define NEG 0.2f

// ---------------- scratch (device globals; no allocation allowed) ----------------
__device__ uint2 g_xlh[NPAD * 32];   // source transform, fp16 (4 halves per uint2)
__device__ uint2 g_xrh[NPAD * 32];   // destination transform, fp16
__device__ float g_h1[NPAD * DIM];   // layer-1 output, fp32 (GEMM input)
__device__ int   g_count[NN];
__device__ int   g_rowptr[NN + 1];
__device__ int   g_cursor[NN];
__device__ int   g_col[ETOT];        // CSR: SOURCE node id, grouped by dst

// ---------------- CSR build ----------------
__global__ void zero_counts_kernel() {
    int i = blockIdx.x * blockDim.x + threadIdx.x;
    if (i < NN) g_count[i] = 0;
}

__global__ void hist_kernel(const int* __restrict__ ei) {
    int e = blockIdx.x * blockDim.x + threadIdx.x;
    if (e >= ETOT) return;
    int dst = (e < EE) ? ei[EE + e] : (e - EE);
    atomicAdd(&g_count[dst], 1);
}

__global__ void scan_kernel() {
    const int T = 1024;
    const int CH = (NN + T - 1) / T;   // 49
    int t = threadIdx.x;
    int b = t * CH;
    int e = min(b + CH, NN);
    int s = 0;
    for (int i = b; i < e; i++) s += g_count[i];
    __shared__ int sh[T];
    sh[t] = s;
    __syncthreads();
    for (int off = 1; off < T; off <<= 1) {
        int v = (t >= off) ? sh[t - off] : 0;
        __syncthreads();
        sh[t] += v;
        __syncthreads();
    }
    int run = (t == 0) ? 0 : sh[t - 1];
    for (int i = b; i < e; i++) {
        int c = g_count[i];
        g_rowptr[i] = run;
        g_cursor[i] = run;
        run += c;
    }
    if (t == 0) g_rowptr[NN] = sh[T - 1];
}

__global__ void scatter_kernel(const int* __restrict__ ei) {
    int e = blockIdx.x * blockDim.x + threadIdx.x;
    if (e >= ETOT) return;
    int src = (e < EE) ? ei[e] : (e - EE);
    int dst = (e < EE) ? ei[EE + e] : (e - EE);
    int p = atomicAdd(&g_cursor[dst], 1);
    g_col[p] = src;
}

// ---------------- Dual GEMM via fp16 tensor cores (HMMA m16n16k16) --------------
// Per block: 128 rows x 256 cols (Wl's 128 ++ Wr's 128), K=128 in 32-chunks.
// 8 warps: warp w owns row group w*16, ALL 16 col-fragments (16 acc frags).
// B-fragment smem loads amortized over 2x the rows vs previous version.
// Epilogue: 4 waves (2 row-halves x 2 col-halves) via 64x132 fp32 smem buffer.
__global__ void __launch_bounds__(256, 1) gemm_half_kernel(
        const float* __restrict__ A, const float* __restrict__ Wl,
        const float* __restrict__ Wr, int M) {
    __shared__ __align__(16) char sm[34048];
    __half* As = (__half*)sm;                       // 128 x 48 halves (12288 B)
    __half* Ws = (__half*)(sm + 12288);             // 32 x 264 halves (16896 B)
    float (*Cs)[132] = (float(*)[132])sm;           // epilogue reuse (33792 B)

    int tid = threadIdx.x;
    int w = tid >> 5;
    int m0 = blockIdx.x * 128;

    wmma::fragment<wmma::accumulator, 16, 16, 16, float> acc[16];
    #pragma unroll
    for (int j = 0; j < 16; j++) wmma::fill_fragment(acc[j], 0.0f);

    for (int k0 = 0; k0 < 128; k0 += 32) {
        // A chunk 128x32 -> fp16 smem (stride 48 halves = 96 B)
        {
            int r = tid >> 1, c = (tid & 1) * 16;
            float4 f0 = make_float4(0.f,0.f,0.f,0.f), f1 = f0, f2 = f0, f3 = f0;
            if (m0 + r < M) {
                const float* p = &A[(size_t)(m0 + r) * 128 + k0 + c];
                f0 = *(const float4*)p;       f1 = *(const float4*)(p + 4);
                f2 = *(const float4*)(p + 8); f3 = *(const float4*)(p + 12);
            }
            __half2 h0 = __floats2half2_rn(f0.x, f0.y), h1 = __floats2half2_rn(f0.z, f0.w);
            __half2 h2 = __floats2half2_rn(f1.x, f1.y), h3 = __floats2half2_rn(f1.z, f1.w);
            __half2 h4 = __floats2half2_rn(f2.x, f2.y), h5 = __floats2half2_rn(f2.z, f2.w);
            __half2 h6 = __floats2half2_rn(f3.x, f3.y), h7 = __floats2half2_rn(f3.z, f3.w);
            uint4 u0, u1;
            u0.x = *(unsigned*)&h0; u0.y = *(unsigned*)&h1;
            u0.z = *(unsigned*)&h2; u0.w = *(unsigned*)&h3;
            u1.x = *(unsigned*)&h4; u1.y = *(unsigned*)&h5;
            u1.z = *(unsigned*)&h6; u1.w = *(unsigned*)&h7;
            *(uint4*)&As[r * 48 + c]     = u0;
            *(uint4*)&As[r * 48 + c + 8] = u1;
        }
        // W chunk 32 x 256 (Wl cols 0-127, Wr cols 128-255) -> fp16 smem (stride 264)
        {
            int kk = tid >> 3, c = (tid & 7) * 32;
            const float* src = (c < 128) ? Wl : Wr;
            int scol = c & 127;
            const float* p = &src[(size_t)(k0 + kk) * 128 + scol];
            #pragma unroll
            for (int q = 0; q < 4; q++) {
                float4 f0 = *(const float4*)(p + q * 8);
                float4 f1 = *(const float4*)(p + q * 8 + 4);
                __half2 h0 = __floats2half2_rn(f0.x, f0.y);
                __half2 h1 = __floats2half2_rn(f0.z, f0.w);
                __half2 h2 = __floats2half2_rn(f1.x, f1.y);
                __half2 h3 = __floats2half2_rn(f1.z, f1.w);
                uint4 u;
                u.x = *(unsigned*)&h0; u.y = *(unsigned*)&h1;
                u.z = *(unsigned*)&h2; u.w = *(unsigned*)&h3;
                *(uint4*)&Ws[kk * 264 + c + q * 8] = u;
            }
        }
        __syncthreads();
        #pragma unroll
        for (int ks = 0; ks < 32; ks += 16) {
            wmma::fragment<wmma::matrix_a, 16, 16, 16, __half, wmma::row_major> af;
            wmma::load_matrix_sync(af, &As[(w * 16) * 48 + ks], 48);
            #pragma unroll
            for (int j = 0; j < 16; j++) {
                wmma::fragment<wmma::matrix_b, 16, 16, 16, __half, wmma::row_major> bf;
                wmma::load_matrix_sync(bf, &Ws[ks * 264 + j * 16], 264);
                wmma::mma_sync(acc[j], af, bf, acc[j]);
            }
        }
        __syncthreads();
    }

    // Epilogue: 4 waves (row-half rh, col-half hf) through 64x132 fp32 smem.
    #pragma unroll
    for (int rh = 0; rh < 2; rh++) {
        #pragma unroll
        for (int hf = 0; hf < 2; hf++) {
            if ((w >> 2) == rh) {
                int rl = w & 3;
                #pragma unroll
                for (int j2 = 0; j2 < 8; j2++)
                    wmma::store_matrix_sync(&Cs[rl * 16][j2 * 16], acc[hf * 8 + j2],
                                            132, wmma::mem_row_major);
            }
            __syncthreads();
            {
                int r = tid >> 2, cb = (tid & 3) * 8;
                uint2* dst = hf ? g_xrh : g_xlh;
                size_t base = (size_t)(m0 + rh * 64 + r) * 32 + cb;
                #pragma unroll
                for (int j = 0; j < 8; j++) {
                    float4 f = *(const float4*)&Cs[r][(cb + j) * 4];
                    __half2 h0 = __floats2half2_rn(f.x, f.y);
                    __half2 h1 = __floats2half2_rn(f.z, f.w);
                    uint2 u;
                    u.x = *(unsigned*)&h0; u.y = *(unsigned*)&h1;
                    dst[base + j] = u;
                }
            }
            __syncthreads();
        }
    }
}

// ---------------- Fused online-softmax GAT aggregation ----------------
// One warp per destination node; depth-2 prefetch of gathered fp16 rows.
// mode 0: g_h1 = relu(agg + b)          (concat heads, 128-wide fp32)
// mode 1: outp = relu(mean_h(agg) + b)  (32-wide fp32)
__global__ void __launch_bounds__(256) agg_fused_kernel(
        const float* __restrict__ att, const float* __restrict__ bias,
        float* __restrict__ outp, int mode) {
    int d = (blockIdx.x * blockDim.x + threadIdx.x) >> 5;
    int l = threadIdx.x & 31;
    if (d >= NN) return;
    int s0 = g_rowptr[d], s1 = g_rowptr[d + 1];

    float4 a4 = ((const float4*)att)[l];
    uint2 qraw = g_xrh[(size_t)d * 32 + l];
    float2 q01 = __half22float2(*(__half2*)&qraw.x);
    float2 q23 = __half22float2(*(__half2*)&qraw.y);

    float m = -1e30f, den = 0.f;
    float4 acc = make_float4(0.f, 0.f, 0.f, 0.f);

    uint2 p0 = make_uint2(0u, 0u), p1 = make_uint2(0u, 0u);
    if (s0 < s1)     p0 = g_xlh[(size_t)g_col[s0] * 32 + l];
    if (s0 + 1 < s1) p1 = g_xlh[(size_t)g_col[s0 + 1] * 32 + l];

    for (int i = s0; i < s1; i++) {
        uint2 raw = p0;
        p0 = p1;
        if (i + 2 < s1) p1 = g_xlh[(size_t)g_col[i + 2] * 32 + l];

        float2 v01 = __half22float2(*(__half2*)&raw.x);
        float2 v23 = __half22float2(*(__half2*)&raw.y);

        float ex = v01.x + q01.x, ey = v01.y + q01.y;
        float ez = v23.x + q23.x, ew = v23.y + q23.y;
        float lx = (ex > 0.f) ? ex : NEG * ex;
        float ly = (ey > 0.f) ? ey : NEG * ey;
        float lz = (ez > 0.f) ? ez : NEG * ez;
        float lw = (ew > 0.f) ? ew : NEG * ew;
        float t = lx * a4.x + ly * a4.y + lz * a4.z + lw * a4.w;
        t += __shfl_xor_sync(0xffffffffu, t, 1, 8);
        t += __shfl_xor_sync(0xffffffffu, t, 2, 8);
        t += __shfl_xor_sync(0xffffffffu, t, 4, 8);

        float mnew = fmaxf(m, t);
        float corr = __expf(m - mnew);
        float wgt = __expf(t - mnew);
        den = den * corr + wgt;
        acc.x = acc.x * corr + wgt * v01.x;
        acc.y = acc.y * corr + wgt * v01.y;
        acc.z = acc.z * corr + wgt * v23.x;
        acc.w = acc.w * corr + wgt * v23.y;
        m = mnew;
    }

    float invdn = 1.0f / den;
    acc.x *= invdn; acc.y *= invdn; acc.z *= invdn; acc.w *= invdn;

    if (mode == 0) {
        float4 b = ((const float4*)bias)[l];
        float4 o;
        o.x = fmaxf(acc.x + b.x, 0.f);
        o.y = fmaxf(acc.y + b.y, 0.f);
        o.z = fmaxf(acc.z + b.z, 0.f);
        o.w = fmaxf(acc.w + b.w, 0.f);
        ((float4*)g_h1)[(size_t)d * 32 + l] = o;
    } else {
        acc.x += __shfl_xor_sync(0xffffffffu, acc.x, 8);
        acc.y += __shfl_xor_sync(0xffffffffu, acc.y, 8);
        acc.z += __shfl_xor_sync(0xffffffffu, acc.z, 8);
        acc.w += __shfl_xor_sync(0xffffffffu, acc.w, 8);
        acc.x += __shfl_xor_sync(0xffffffffu, acc.x, 16);
        acc.y += __shfl_xor_sync(0xffffffffu, acc.y, 16);
        acc.z += __shfl_xor_sync(0xffffffffu, acc.z, 16);
        acc.w += __shfl_xor_sync(0xffffffffu, acc.w, 16);
        if (l < 8) {
            float4 b = ((const float4*)bias)[l];
            float4 o;
            o.x = fmaxf(acc.x * 0.25f + b.x, 0.f);
            o.y = fmaxf(acc.y * 0.25f + b.y, 0.f);
            o.z = fmaxf(acc.z * 0.25f + b.z, 0.f);
            o.w = fmaxf(acc.w * 0.25f + b.w, 0.f);
            ((float4*)outp)[(size_t)d * 8 + l] = o;
        }
    }
}

// ---------------- launch ----------------
// Launch order puts gemm_half at position 4 (the launch ncu consistently captures)
// to get GEMM attribution next round. Dependencies remain valid:
// gemm1 needs nothing from the CSR; scatter needs hist+scan; agg1 needs scatter+gemm1.
extern "C" void kernel_launch(void* const* d_in, const int* in_sizes, int n_in,
                              void* d_out, int out_size) {
    const float* x    = (const float*)d_in[0];
    const int*   ei   = (const int*)d_in[1];
    const float* Wl1  = (const float*)d_in[2];
    const float* Wr1  = (const float*)d_in[3];
    const float* att1 = (const float*)d_in[4];
    const float* b1   = (const float*)d_in[5];
    const float* Wl2  = (const float*)d_in[6];
    const float* Wr2  = (const float*)d_in[7];
    const float* att2 = (const float*)d_in[8];
    const float* b2   = (const float*)d_in[9];
    float* out = (float*)d_out;

    float* d_h1; cudaGetSymbolAddress((void**)&d_h1, g_h1);

    int gemm_blocks = NPAD / 128;                  // 391
    int agg_blocks = (NN * 32 + 255) / 256;        // one warp per dst

    zero_counts_kernel<<<(NN + 255) / 256, 256>>>();               // 1
    hist_kernel<<<(ETOT + 255) / 256, 256>>>(ei);                  // 2
    scan_kernel<<<1, 1024>>>();                                    // 3
    gemm_half_kernel<<<gemm_blocks, 256>>>(x, Wl1, Wr1, NN);       // 4 (probed)
    scatter_kernel<<<(ETOT + 255) / 256, 256>>>(ei);               // 5
    agg_fused_kernel<<<agg_blocks, 256>>>(att1, b1, nullptr, 0);   // 6 -> g_h1
    gemm_half_kernel<<<gemm_blocks, 256>>>(d_h1, Wl2, Wr2, NN);    // 7
    agg_fused_kernel<<<agg_blocks, 256>>>(att2, b2, out, 1);       // 8 -> d_out
}

// round 9
// speedup vs baseline: 1.7443x; 1.0012x over previous
#include <cuda_runtime.h>
#include <cuda_fp16.h>
#include <mma.h>
using namespace nvcuda;

#define NN 50000
#define NPAD 50048    // 391 * 128, padded rows for unguarded stores
#define EE 800000
#define ETOT 850000   // EE + NN self loops
#define DIM 128       // 4 heads * 32
#define NEG 0.2f

// ---------------- scratch (device globals; no allocation allowed) ----------------
__device__ uint2 g_xlh[NPAD * 32];   // source transform, fp16 (4 halves per uint2)
__device__ uint2 g_xrh[NPAD * 32];   // destination transform, fp16
__device__ float g_h1[NPAD * DIM];   // layer-1 output, fp32 (GEMM input)
__device__ int   g_count[NN];        // zero at start of every call (BSS init / scan self-clear)
__device__ int   g_rowptr[NN + 1];
__device__ int   g_cursor[NN];
__device__ int   g_col[ETOT];        // CSR: SOURCE node id, grouped by dst

// ---------------- CSR build ----------------
__global__ void hist_kernel(const int* __restrict__ ei) {
    int e = blockIdx.x * blockDim.x + threadIdx.x;
    if (e >= ETOT) return;
    int dst = (e < EE) ? ei[EE + e] : (e - EE);
    atomicAdd(&g_count[dst], 1);
}

// Prefix sum; re-zeroes g_count after reading so the next invocation's hist
// starts from zero (keeps the launch graph deterministic without a zero pass).
__global__ void scan_kernel() {
    const int T = 1024;
    const int CH = (NN + T - 1) / T;   // 49
    int t = threadIdx.x;
    int b = t * CH;
    int e = min(b + CH, NN);
    int s = 0;
    for (int i = b; i < e; i++) s += g_count[i];
    __shared__ int sh[T];
    sh[t] = s;
    __syncthreads();
    for (int off = 1; off < T; off <<= 1) {
        int v = (t >= off) ? sh[t - off] : 0;
        __syncthreads();
        sh[t] += v;
        __syncthreads();
    }
    int run = (t == 0) ? 0 : sh[t - 1];
    for (int i = b; i < e; i++) {
        int c = g_count[i];
        g_count[i] = 0;          // self-clear for next invocation
        g_rowptr[i] = run;
        g_cursor[i] = run;
        run += c;
    }
    if (t == 0) g_rowptr[NN] = sh[T - 1];
}

__global__ void scatter_kernel(const int* __restrict__ ei) {
    int e = blockIdx.x * blockDim.x + threadIdx.x;
    if (e >= ETOT) return;
    int src = (e < EE) ? ei[e] : (e - EE);
    int dst = (e < EE) ? ei[EE + e] : (e - EE);
    int p = atomicAdd(&g_cursor[dst], 1);
    g_col[p] = src;
}

// ---------------- Dual GEMM via fp16 tensor cores (HMMA m16n16k16) --------------
// Per block: 128 rows x 256 cols (Wl's 128 ++ Wr's 128), K=128 in 32-chunks.
// 8 warps: warp w owns row group w*16, ALL 16 col-fragments (16 acc frags).
// As stride 56 halves (112 B) -> 2-way (was 4-way) bank conflicts on A-frag loads.
__global__ void __launch_bounds__(256, 1) gemm_half_kernel(
        const float* __restrict__ A, const float* __restrict__ Wl,
        const float* __restrict__ Wr, int M) {
    __shared__ __align__(16) char sm[34048];
    __half* As = (__half*)sm;                       // 128 x 56 halves (14336 B)
    __half* Ws = (__half*)(sm + 14336);             // 32 x 264 halves (16896 B)
    float (*Cs)[132] = (float(*)[132])sm;           // epilogue reuse (33792 B)

    int tid = threadIdx.x;
    int w = tid >> 5;
    int m0 = blockIdx.x * 128;

    wmma::fragment<wmma::accumulator, 16, 16, 16, float> acc[16];
    #pragma unroll
    for (int j = 0; j < 16; j++) wmma::fill_fragment(acc[j], 0.0f);

    for (int k0 = 0; k0 < 128; k0 += 32) {
        // A chunk 128x32 -> fp16 smem (stride 56 halves = 112 B)
        {
            int r = tid >> 1, c = (tid & 1) * 16;
            float4 f0 = make_float4(0.f,0.f,0.f,0.f), f1 = f0, f2 = f0, f3 = f0;
            if (m0 + r < M) {
                const float* p = &A[(size_t)(m0 + r) * 128 + k0 + c];
                f0 = *(const float4*)p;       f1 = *(const float4*)(p + 4);
                f2 = *(const float4*)(p + 8); f3 = *(const float4*)(p + 12);
            }
            __half2 h0 = __floats2half2_rn(f0.x, f0.y), h1 = __floats2half2_rn(f0.z, f0.w);
            __half2 h2 = __floats2half2_rn(f1.x, f1.y), h3 = __floats2half2_rn(f1.z, f1.w);
            __half2 h4 = __floats2half2_rn(f2.x, f2.y), h5 = __floats2half2_rn(f2.z, f2.w);
            __half2 h6 = __floats2half2_rn(f3.x, f3.y), h7 = __floats2half2_rn(f3.z, f3.w);
            uint4 u0, u1;
            u0.x = *(unsigned*)&h0; u0.y = *(unsigned*)&h1;
            u0.z = *(unsigned*)&h2; u0.w = *(unsigned*)&h3;
            u1.x = *(unsigned*)&h4; u1.y = *(unsigned*)&h5;
            u1.z = *(unsigned*)&h6; u1.w = *(unsigned*)&h7;
            *(uint4*)&As[r * 56 + c]     = u0;
            *(uint4*)&As[r * 56 + c + 8] = u1;
        }
        // W chunk 32 x 256 (Wl cols 0-127, Wr cols 128-255) -> fp16 smem (stride 264)
        {
            int kk = tid >> 3, c = (tid & 7) * 32;
            const float* src = (c < 128) ? Wl : Wr;
            int scol = c & 127;
            const float* p = &src[(size_t)(k0 + kk) * 128 + scol];
            #pragma unroll
            for (int q = 0; q < 4; q++) {
                float4 f0 = *(const float4*)(p + q * 8);
                float4 f1 = *(const float4*)(p + q * 8 + 4);
                __half2 h0 = __floats2half2_rn(f0.x, f0.y);
                __half2 h1 = __floats2half2_rn(f0.z, f0.w);
                __half2 h2 = __floats2half2_rn(f1.x, f1.y);
                __half2 h3 = __floats2half2_rn(f1.z, f1.w);
                uint4 u;
                u.x = *(unsigned*)&h0; u.y = *(unsigned*)&h1;
                u.z = *(unsigned*)&h2; u.w = *(unsigned*)&h3;
                *(uint4*)&Ws[kk * 264 + c + q * 8] = u;
            }
        }
        __syncthreads();
        #pragma unroll
        for (int ks = 0; ks < 32; ks += 16) {
            wmma::fragment<wmma::matrix_a, 16, 16, 16, __half, wmma::row_major> af;
            wmma::load_matrix_sync(af, &As[(w * 16) * 56 + ks], 56);
            #pragma unroll
            for (int j = 0; j < 16; j++) {
                wmma::fragment<wmma::matrix_b, 16, 16, 16, __half, wmma::row_major> bf;
                wmma::load_matrix_sync(bf, &Ws[ks * 264 + j * 16], 264);
                wmma::mma_sync(acc[j], af, bf, acc[j]);
            }
        }
        __syncthreads();
    }

    // Epilogue: 4 waves (row-half rh, col-half hf) through 64x132 fp32 smem.
    #pragma unroll
    for (int rh = 0; rh < 2; rh++) {
        #pragma unroll
        for (int hf = 0; hf < 2; hf++) {
            if ((w >> 2) == rh) {
                int rl = w & 3;
                #pragma unroll
                for (int j2 = 0; j2 < 8; j2++)
                    wmma::store_matrix_sync(&Cs[rl * 16][j2 * 16], acc[hf * 8 + j2],
                                            132, wmma::mem_row_major);
            }
            __syncthreads();
            {
                int r = tid >> 2, cb = (tid & 3) * 8;
                uint2* dst = hf ? g_xrh : g_xlh;
                size_t base = (size_t)(m0 + rh * 64 + r) * 32 + cb;
                #pragma unroll
                for (int j = 0; j < 8; j++) {
                    float4 f = *(const float4*)&Cs[r][(cb + j) * 4];
                    __half2 h0 = __floats2half2_rn(f.x, f.y);
                    __half2 h1 = __floats2half2_rn(f.z, f.w);
                    uint2 u;
                    u.x = *(unsigned*)&h0; u.y = *(unsigned*)&h1;
                    dst[base + j] = u;
                }
            }
            __syncthreads();
        }
    }
}

// ---------------- Fused GAT aggregation (softmax without max-shift) ----------------
// One warp per destination node; depth-2 prefetch. Softmax computed as
// sum(exp(t))-normalized directly: mathematically identical to max-shifted
// softmax, and logits here are O(1-10) so exp cannot overflow/underflow to 0
// for all edges of a node (every node has a self loop).
// Removing the online-max recurrence makes consecutive edges independent ->
// the SHFL/MUFU chains of different edges pipeline.
// mode 0: g_h1 = relu(agg + b)          (concat heads, 128-wide fp32)
// mode 1: outp = relu(mean_h(agg) + b)  (32-wide fp32)
__global__ void __launch_bounds__(256) agg_fused_kernel(
        const float* __restrict__ att, const float* __restrict__ bias,
        float* __restrict__ outp, int mode) {
    int d = (blockIdx.x * blockDim.x + threadIdx.x) >> 5;
    int l = threadIdx.x & 31;
    if (d >= NN) return;
    int s0 = g_rowptr[d], s1 = g_rowptr[d + 1];

    float4 a4 = ((const float4*)att)[l];
    uint2 qraw = g_xrh[(size_t)d * 32 + l];
    float2 q01 = __half22float2(*(__half2*)&qraw.x);
    float2 q23 = __half22float2(*(__half2*)&qraw.y);

    float den = 0.f;
    float4 acc = make_float4(0.f, 0.f, 0.f, 0.f);

    uint2 p0 = make_uint2(0u, 0u), p1 = make_uint2(0u, 0u);
    if (s0 < s1)     p0 = g_xlh[(size_t)g_col[s0] * 32 + l];
    if (s0 + 1 < s1) p1 = g_xlh[(size_t)g_col[s0 + 1] * 32 + l];

    for (int i = s0; i < s1; i++) {
        uint2 raw = p0;
        p0 = p1;
        if (i + 2 < s1) p1 = g_xlh[(size_t)g_col[i + 2] * 32 + l];

        float2 v01 = __half22float2(*(__half2*)&raw.x);
        float2 v23 = __half22float2(*(__half2*)&raw.y);

        float ex = v01.x + q01.x, ey = v01.y + q01.y;
        float ez = v23.x + q23.x, ew = v23.y + q23.y;
        float lx = (ex > 0.f) ? ex : NEG * ex;
        float ly = (ey > 0.f) ? ey : NEG * ey;
        float lz = (ez > 0.f) ? ez : NEG * ez;
        float lw = (ew > 0.f) ? ew : NEG * ew;
        float t = lx * a4.x + ly * a4.y + lz * a4.z + lw * a4.w;
        t += __shfl_xor_sync(0xffffffffu, t, 1, 8);
        t += __shfl_xor_sync(0xffffffffu, t, 2, 8);
        t += __shfl_xor_sync(0xffffffffu, t, 4, 8);

        float wgt = __expf(t);
        den += wgt;
        acc.x += wgt * v01.x;
        acc.y += wgt * v01.y;
        acc.z += wgt * v23.x;
        acc.w += wgt * v23.y;
    }

    float invdn = 1.0f / den;
    acc.x *= invdn; acc.y *= invdn; acc.z *= invdn; acc.w *= invdn;

    if (mode == 0) {
        float4 b = ((const float4*)bias)[l];
        float4 o;
        o.x = fmaxf(acc.x + b.x, 0.f);
        o.y = fmaxf(acc.y + b.y, 0.f);
        o.z = fmaxf(acc.z + b.z, 0.f);
        o.w = fmaxf(acc.w + b.w, 0.f);
        ((float4*)g_h1)[(size_t)d * 32 + l] = o;
    } else {
        acc.x += __shfl_xor_sync(0xffffffffu, acc.x, 8);
        acc.y += __shfl_xor_sync(0xffffffffu, acc.y, 8);
        acc.z += __shfl_xor_sync(0xffffffffu, acc.z, 8);
        acc.w += __shfl_xor_sync(0xffffffffu, acc.w, 8);
        acc.x += __shfl_xor_sync(0xffffffffu, acc.x, 16);
        acc.y += __shfl_xor_sync(0xffffffffu, acc.y, 16);
        acc.z += __shfl_xor_sync(0xffffffffu, acc.z, 16);
        acc.w += __shfl_xor_sync(0xffffffffu, acc.w, 16);
        if (l < 8) {
            float4 b = ((const float4*)bias)[l];
            float4 o;
            o.x = fmaxf(acc.x * 0.25f + b.x, 0.f);
            o.y = fmaxf(acc.y * 0.25f + b.y, 0.f);
            o.z = fmaxf(acc.z * 0.25f + b.z, 0.f);
            o.w = fmaxf(acc.w * 0.25f + b.w, 0.f);
            ((float4*)outp)[(size_t)d * 8 + l] = o;
        }
    }
}

// ---------------- launch ----------------
// gemm1 stays at captured slot 4 (profile comparability across rounds).
extern "C" void kernel_launch(void* const* d_in, const int* in_sizes, int n_in,
                              void* d_out, int out_size) {
    const float* x    = (const float*)d_in[0];
    const int*   ei   = (const int*)d_in[1];
    const float* Wl1  = (const float*)d_in[2];
    const float* Wr1  = (const float*)d_in[3];
    const float* att1 = (const float*)d_in[4];
    const float* b1   = (const float*)d_in[5];
    const float* Wl2  = (const float*)d_in[6];
    const float* Wr2  = (const float*)d_in[7];
    const float* att2 = (const float*)d_in[8];
    const float* b2   = (const float*)d_in[9];
    float* out = (float*)d_out;

    float* d_h1; cudaGetSymbolAddress((void**)&d_h1, g_h1);

    int gemm_blocks = NPAD / 128;                  // 391
    int agg_blocks = (NN * 32 + 255) / 256;        // one warp per dst

    hist_kernel<<<(ETOT + 255) / 256, 256>>>(ei);                  // 1
    scan_kernel<<<1, 1024>>>();                                    // 2 (self-clears g_count)
    scatter_kernel<<<(ETOT + 255) / 256, 256>>>(ei);               // 3
    gemm_half_kernel<<<gemm_blocks, 256>>>(x, Wl1, Wr1, NN);       // 4 (probed)
    agg_fused_kernel<<<agg_blocks, 256>>>(att1, b1, nullptr, 0);   // 5 -> g_h1
    gemm_half_kernel<<<gemm_blocks, 256>>>(d_h1, Wl2, Wr2, NN);    // 6
    agg_fused_kernel<<<agg_blocks, 256>>>(att2, b2, out, 1);       // 7 -> d_out
}

// round 11
// speedup vs baseline: 1.8192x; 1.0430x over previous
#include <cuda_runtime.h>
#include <cuda_fp16.h>
#include <mma.h>
using namespace nvcuda;

#define NN 50000
#define NPAD 50048    // 391 * 128, padded rows for unguarded stores
#define EE 800000
#define ETOT 850000   // EE + NN self loops
#define DIM 128       // 4 heads * 32
#define NEG 0.2f

// ---------------- scratch (device globals; no allocation allowed) ----------------
// fp16 node tables: row = 16 uint4 = 128 halves.
__device__ uint4 g_xlh[NPAD * 16];   // source transform, fp16
__device__ uint4 g_xrh[NPAD * 16];   // destination transform, fp16
__device__ float g_h1[NPAD * DIM];   // layer-1 output, fp32 (GEMM input)
__device__ int   g_count[NN];        // zero at start of every call (BSS init / scan self-clear)
__device__ int   g_rowptr[NN + 1];
__device__ int   g_cursor[NN];
__device__ int   g_col[ETOT];        // CSR: SOURCE node id, grouped by dst

// ---------------- CSR build ----------------
__global__ void hist_kernel(const int* __restrict__ ei) {
    int e = blockIdx.x * blockDim.x + threadIdx.x;
    if (e >= ETOT) return;
    int dst = (e < EE) ? ei[EE + e] : (e - EE);
    atomicAdd(&g_count[dst], 1);
}

// Prefix sum; re-zeroes g_count after reading so the next invocation starts clean.
__global__ void scan_kernel() {
    const int T = 1024;
    const int CH = (NN + T - 1) / T;   // 49
    int t = threadIdx.x;
    int b = t * CH;
    int e = min(b + CH, NN);
    int s = 0;
    for (int i = b; i < e; i++) s += g_count[i];
    __shared__ int sh[T];
    sh[t] = s;
    __syncthreads();
    for (int off = 1; off < T; off <<= 1) {
        int v = (t >= off) ? sh[t - off] : 0;
        __syncthreads();
        sh[t] += v;
        __syncthreads();
    }
    int run = (t == 0) ? 0 : sh[t - 1];
    for (int i = b; i < e; i++) {
        int c = g_count[i];
        g_count[i] = 0;          // self-clear for next invocation
        g_rowptr[i] = run;
        g_cursor[i] = run;
        run += c;
    }
    if (t == 0) g_rowptr[NN] = sh[T - 1];
}

__global__ void scatter_kernel(const int* __restrict__ ei) {
    int e = blockIdx.x * blockDim.x + threadIdx.x;
    if (e >= ETOT) return;
    int src = (e < EE) ? ei[e] : (e - EE);
    int dst = (e < EE) ? ei[EE + e] : (e - EE);
    int p = atomicAdd(&g_cursor[dst], 1);
    g_col[p] = src;
}

// ---------------- Dual GEMM via fp16 tensor cores (HMMA m16n16k16) --------------
__global__ void __launch_bounds__(256, 1) gemm_half_kernel(
        const float* __restrict__ A, const float* __restrict__ Wl,
        const float* __restrict__ Wr, int M) {
    __shared__ __align__(16) char sm[34048];
    __half* As = (__half*)sm;                       // 128 x 56 halves (14336 B)
    __half* Ws = (__half*)(sm + 14336);             // 32 x 264 halves (16896 B)
    float (*Cs)[132] = (float(*)[132])sm;           // epilogue reuse (33792 B)

    int tid = threadIdx.x;
    int w = tid >> 5;
    int m0 = blockIdx.x * 128;

    wmma::fragment<wmma::accumulator, 16, 16, 16, float> acc[16];
    #pragma unroll
    for (int j = 0; j < 16; j++) wmma::fill_fragment(acc[j], 0.0f);

    for (int k0 = 0; k0 < 128; k0 += 32) {
        {
            int r = tid >> 1, c = (tid & 1) * 16;
            float4 f0 = make_float4(0.f,0.f,0.f,0.f), f1 = f0, f2 = f0, f3 = f0;
            if (m0 + r < M) {
                const float* p = &A[(size_t)(m0 + r) * 128 + k0 + c];
                f0 = *(const float4*)p;       f1 = *(const float4*)(p + 4);
                f2 = *(const float4*)(p + 8); f3 = *(const float4*)(p + 12);
            }
            __half2 h0 = __floats2half2_rn(f0.x, f0.y), h1 = __floats2half2_rn(f0.z, f0.w);
            __half2 h2 = __floats2half2_rn(f1.x, f1.y), h3 = __floats2half2_rn(f1.z, f1.w);
            __half2 h4 = __floats2half2_rn(f2.x, f2.y), h5 = __floats2half2_rn(f2.z, f2.w);
            __half2 h6 = __floats2half2_rn(f3.x, f3.y), h7 = __floats2half2_rn(f3.z, f3.w);
            uint4 u0, u1;
            u0.x = *(unsigned*)&h0; u0.y = *(unsigned*)&h1;
            u0.z = *(unsigned*)&h2; u0.w = *(unsigned*)&h3;
            u1.x = *(unsigned*)&h4; u1.y = *(unsigned*)&h5;
            u1.z = *(unsigned*)&h6; u1.w = *(unsigned*)&h7;
            *(uint4*)&As[r * 56 + c]     = u0;
            *(uint4*)&As[r * 56 + c + 8] = u1;
        }
        {
            int kk = tid >> 3, c = (tid & 7) * 32;
            const float* src = (c < 128) ? Wl : Wr;
            int scol = c & 127;
            const float* p = &src[(size_t)(k0 + kk) * 128 + scol];
            #pragma unroll
            for (int q = 0; q < 4; q++) {
                float4 f0 = *(const float4*)(p + q * 8);
                float4 f1 = *(const float4*)(p + q * 8 + 4);
                __half2 h0 = __floats2half2_rn(f0.x, f0.y);
                __half2 h1 = __floats2half2_rn(f0.z, f0.w);
                __half2 h2 = __floats2half2_rn(f1.x, f1.y);
                __half2 h3 = __floats2half2_rn(f1.z, f1.w);
                uint4 u;
                u.x = *(unsigned*)&h0; u.y = *(unsigned*)&h1;
                u.z = *(unsigned*)&h2; u.w = *(unsigned*)&h3;
                *(uint4*)&Ws[kk * 264 + c + q * 8] = u;
            }
        }
        __syncthreads();
        #pragma unroll
        for (int ks = 0; ks < 32; ks += 16) {
            wmma::fragment<wmma::matrix_a, 16, 16, 16, __half, wmma::row_major> af;
            wmma::load_matrix_sync(af, &As[(w * 16) * 56 + ks], 56);
            #pragma unroll
            for (int j = 0; j < 16; j++) {
                wmma::fragment<wmma::matrix_b, 16, 16, 16, __half, wmma::row_major> bf;
                wmma::load_matrix_sync(bf, &Ws[ks * 264 + j * 16], 264);
                wmma::mma_sync(acc[j], af, bf, acc[j]);
            }
        }
        __syncthreads();
    }

    // Epilogue: 4 waves (row-half rh, col-half hf) through 64x132 fp32 smem.
    #pragma unroll
    for (int rh = 0; rh < 2; rh++) {
        #pragma unroll
        for (int hf = 0; hf < 2; hf++) {
            if ((w >> 2) == rh) {
                int rl = w & 3;
                #pragma unroll
                for (int j2 = 0; j2 < 8; j2++)
                    wmma::store_matrix_sync(&Cs[rl * 16][j2 * 16], acc[hf * 8 + j2],
                                            132, wmma::mem_row_major);
            }
            __syncthreads();
            {
                int r = tid >> 2, cb = (tid & 3) * 4;   // uint4 index within row (16/row)
                uint4* dst = hf ? g_xrh : g_xlh;
                size_t base = (size_t)(m0 + rh * 64 + r) * 16 + cb;
                #pragma unroll
                for (int j = 0; j < 4; j++) {
                    float4 fA = *(const float4*)&Cs[r][(cb + j) * 8];
                    float4 fB = *(const float4*)&Cs[r][(cb + j) * 8 + 4];
                    __half2 h0 = __floats2half2_rn(fA.x, fA.y);
                    __half2 h1 = __floats2half2_rn(fA.z, fA.w);
                    __half2 h2 = __floats2half2_rn(fB.x, fB.y);
                    __half2 h3 = __floats2half2_rn(fB.z, fB.w);
                    uint4 u;
                    u.x = *(unsigned*)&h0; u.y = *(unsigned*)&h1;
                    u.z = *(unsigned*)&h2; u.w = *(unsigned*)&h3;
                    dst[base + j] = u;
                }
            }
            __syncthreads();
        }
    }
}

// ---------------- Fused GAT aggregation: half-warp per edge ----------------
// One warp per destination node; each 16-lane half processes one edge per trip
// (2 edges/warp/trip). Lane owns 8 feature dims (one uint4 of fp16).
// Softmax without max-shift (validated R9). Cross-half combine at the end.
// mode 0: g_h1 = relu(agg + b)          (concat heads, 128-wide fp32)
// mode 1: outp = relu(mean_h(agg) + b)  (32-wide fp32)
__global__ void __launch_bounds__(256) agg_fused_kernel(
        const float* __restrict__ att, const float* __restrict__ bias,
        float* __restrict__ outp, int mode) {
    int d = (blockIdx.x * blockDim.x + threadIdx.x) >> 5;
    int l = threadIdx.x & 31;
    if (d >= NN) return;
    int s0 = g_rowptr[d], s1 = g_rowptr[d + 1];

    int half = l >> 4;
    int hl = l & 15;
    unsigned hmask = 0xFFFFu << (half * 16);

    // att + xr[dst] for this lane's 8 dims [8*hl, 8*hl+8)
    float4 aA = ((const float4*)att)[2 * hl];
    float4 aB = ((const float4*)att)[2 * hl + 1];
    uint4 qr = g_xrh[(size_t)d * 16 + hl];
    float2 q0 = __half22float2(*(__half2*)&qr.x);
    float2 q1 = __half22float2(*(__half2*)&qr.y);
    float2 q2 = __half22float2(*(__half2*)&qr.z);
    float2 q3 = __half22float2(*(__half2*)&qr.w);

    float den = 0.f;
    float ac0 = 0.f, ac1 = 0.f, ac2 = 0.f, ac3 = 0.f;
    float ac4 = 0.f, ac5 = 0.f, ac6 = 0.f, ac7 = 0.f;

    int i = s0 + half;
    uint4 p0 = make_uint4(0u,0u,0u,0u), p1 = p0;
    if (i < s1)     p0 = g_xlh[(size_t)g_col[i] * 16 + hl];
    if (i + 2 < s1) p1 = g_xlh[(size_t)g_col[i + 2] * 16 + hl];

    for (; i < s1; i += 2) {
        uint4 raw = p0;
        p0 = p1;
        int nx = i + 4;
        if (nx < s1) p1 = g_xlh[(size_t)g_col[nx] * 16 + hl];

        float2 v0 = __half22float2(*(__half2*)&raw.x);
        float2 v1 = __half22float2(*(__half2*)&raw.y);
        float2 v2 = __half22float2(*(__half2*)&raw.z);
        float2 v3 = __half22float2(*(__half2*)&raw.w);

        float e0 = v0.x + q0.x, e1 = v0.y + q0.y, e2 = v1.x + q1.x, e3 = v1.y + q1.y;
        float e4 = v2.x + q2.x, e5 = v2.y + q2.y, e6 = v3.x + q3.x, e7 = v3.y + q3.y;
        float t =
            ((e0 > 0.f) ? e0 : NEG * e0) * aA.x +
            ((e1 > 0.f) ? e1 : NEG * e1) * aA.y +
            ((e2 > 0.f) ? e2 : NEG * e2) * aA.z +
            ((e3 > 0.f) ? e3 : NEG * e3) * aA.w +
            ((e4 > 0.f) ? e4 : NEG * e4) * aB.x +
            ((e5 > 0.f) ? e5 : NEG * e5) * aB.y +
            ((e6 > 0.f) ? e6 : NEG * e6) * aB.z +
            ((e7 > 0.f) ? e7 : NEG * e7) * aB.w;
        // reduce over the 4 lanes of this head (groups of 4 within the half)
        t += __shfl_xor_sync(hmask, t, 1, 4);
        t += __shfl_xor_sync(hmask, t, 2, 4);

        float wgt = __expf(t);
        den += wgt;
        ac0 += wgt * v0.x; ac1 += wgt * v0.y; ac2 += wgt * v1.x; ac3 += wgt * v1.y;
        ac4 += wgt * v2.x; ac5 += wgt * v2.y; ac6 += wgt * v3.x; ac7 += wgt * v3.y;
    }

    // combine halves (full-warp, converged after loop)
    den += __shfl_xor_sync(0xffffffffu, den, 16);
    ac0 += __shfl_xor_sync(0xffffffffu, ac0, 16);
    ac1 += __shfl_xor_sync(0xffffffffu, ac1, 16);
    ac2 += __shfl_xor_sync(0xffffffffu, ac2, 16);
    ac3 += __shfl_xor_sync(0xffffffffu, ac3, 16);
    ac4 += __shfl_xor_sync(0xffffffffu, ac4, 16);
    ac5 += __shfl_xor_sync(0xffffffffu, ac5, 16);
    ac6 += __shfl_xor_sync(0xffffffffu, ac6, 16);
    ac7 += __shfl_xor_sync(0xffffffffu, ac7, 16);

    float invdn = 1.0f / den;
    ac0 *= invdn; ac1 *= invdn; ac2 *= invdn; ac3 *= invdn;
    ac4 *= invdn; ac5 *= invdn; ac6 *= invdn; ac7 *= invdn;

    if (mode == 0) {
        // lane (half, hl) writes float4 at dims 8*hl + 4*half
        float4 b = ((const float4*)bias)[2 * hl + half];
        float4 o;
        if (half == 0) {
            o.x = ac0; o.y = ac1; o.z = ac2; o.w = ac3;
        } else {
            o.x = ac4; o.y = ac5; o.z = ac6; o.w = ac7;
        }
        o.x = fmaxf(o.x + b.x, 0.f);
        o.y = fmaxf(o.y + b.y, 0.f);
        o.z = fmaxf(o.z + b.z, 0.f);
        o.w = fmaxf(o.w + b.w, 0.f);
        ((float4*)g_h1)[(size_t)d * 32 + 2 * hl + half] = o;
    } else {
        // mean over heads: sum lanes with same within-head offset (hl&3): xor 4, 8
        ac0 += __shfl_xor_sync(0xffffffffu, ac0, 4);
        ac1 += __shfl_xor_sync(0xffffffffu, ac1, 4);
        ac2 += __shfl_xor_sync(0xffffffffu, ac2, 4);
        ac3 += __shfl_xor_sync(0xffffffffu, ac3, 4);
        ac4 += __shfl_xor_sync(0xffffffffu, ac4, 4);
        ac5 += __shfl_xor_sync(0xffffffffu, ac5, 4);
        ac6 += __shfl_xor_sync(0xffffffffu, ac6, 4);
        ac7 += __shfl_xor_sync(0xffffffffu, ac7, 4);
        ac0 += __shfl_xor_sync(0xffffffffu, ac0, 8);
        ac1 += __shfl_xor_sync(0xffffffffu, ac1, 8);
        ac2 += __shfl_xor_sync(0xffffffffu, ac2, 8);
        ac3 += __shfl_xor_sync(0xffffffffu, ac3, 8);
        ac4 += __shfl_xor_sync(0xffffffffu, ac4, 8);
        ac5 += __shfl_xor_sync(0xffffffffu, ac5, 8);
        ac6 += __shfl_xor_sync(0xffffffffu, ac6, 8);
        ac7 += __shfl_xor_sync(0xffffffffu, ac7, 8);
        if (hl < 4) {
            // lane (half, hl<4) writes float4 at out dims 8*hl + 4*half
            float4 b = ((const float4*)bias)[2 * hl + half];
            float4 o;
            if (half == 0) {
                o.x = ac0; o.y = ac1; o.z = ac2; o.w = ac3;
            } else {
                o.x = ac4; o.y = ac5; o.z = ac6; o.w = ac7;
            }
            o.x = fmaxf(o.x * 0.25f + b.x, 0.f);
            o.y = fmaxf(o.y * 0.25f + b.y, 0.f);
            o.z = fmaxf(o.z * 0.25f + b.z, 0.f);
            o.w = fmaxf(o.w * 0.25f + b.w, 0.f);
            ((float4*)outp)[(size_t)d * 8 + 2 * hl + half] = o;
        }
    }
}

// ---------------- launch ----------------
// gemm1 stays at captured slot 4 (control: should still read ~60 us).
extern "C" void kernel_launch(void* const* d_in, const int* in_sizes, int n_in,
                              void* d_out, int out_size) {
    const float* x    = (const float*)d_in[0];
    const int*   ei   = (const int*)d_in[1];
    const float* Wl1  = (const float*)d_in[2];
    const float* Wr1  = (const float*)d_in[3];
    const float* att1 = (const float*)d_in[4];
    const float* b1   = (const float*)d_in[5];
    const float* Wl2  = (const float*)d_in[6];
    const float* Wr2  = (const float*)d_in[7];
    const float* att2 = (const float*)d_in[8];
    const float* b2   = (const float*)d_in[9];
    float* out = (float*)d_out;

    float* d_h1; cudaGetSymbolAddress((void**)&d_h1, g_h1);

    int gemm_blocks = NPAD / 128;                  // 391
    int agg_blocks = (NN * 32 + 255) / 256;        // one warp per dst

    hist_kernel<<<(ETOT + 255) / 256, 256>>>(ei);                  // 1
    scan_kernel<<<1, 1024>>>();                                    // 2 (self-clears g_count)
    scatter_kernel<<<(ETOT + 255) / 256, 256>>>(ei);               // 3
    gemm_half_kernel<<<gemm_blocks, 256>>>(x, Wl1, Wr1, NN);       // 4 (probed)
    agg_fused_kernel<<<agg_blocks, 256>>>(att1, b1, nullptr, 0);   // 5 -> g_h1
    gemm_half_kernel<<<gemm_blocks, 256>>>(d_h1, Wl2, Wr2, NN);    // 6
    agg_fused_kernel<<<agg_blocks, 256>>>(att2, b2, out, 1);       // 7 -> d_out
}